// round 9
// baseline (speedup 1.0000x reference)
#include <cuda_runtime.h>
#include <math.h>

#define Lc 4
#define Bc 256
#define Sc 256
#define Hc 1024
#define Kc 64
#define NSEC 26
#define PCHUNKS 4
#define SROWS (Sc / PCHUNKS)          // 64
#define POOL_CTAS (PCHUNKS * Bc)      // 1024

// Scratch: partial masked sums, [B][4][H] fp32 = 4 MB
__device__ float g_partial[(size_t)Bc * PCHUNKS * Hc];
// Precomputed projections: P[sec][k][5] = Wu[sec,k,:] @ [Wreg | Word]
__device__ float g_P[NSEC * Kc * 5];
// buW5[sec][5] = bu[sec,:] @ [Wreg | Word]
__device__ float g_buW5[NSEC * 5];

__device__ __forceinline__ float gelu_exact(float x) {
    return 0.5f * x * (1.0f + erff(x * 0.70710678118654752f));
}

__device__ __forceinline__ float warp_sum(float v) {
    #pragma unroll
    for (int o = 16; o; o >>= 1) v += __shfl_down_sync(0xffffffffu, v, o);
    return v;
}

// ---------------------------------------------------------------------------
// Kernel 1: 1050 CTAs, single wave.
//   CTA < 1024 : weighted-layer pooling + masked sum over 64 S-rows.
//   CTA >= 1024: per-section precompute of P and buW5 (26 CTAs, overlapped).
// ---------------------------------------------------------------------------
__global__ __launch_bounds__(256, 8) void pool_pre_kernel(
    const float* __restrict__ hidden,   // [L,B,S,H]
    const int*   __restrict__ mask,     // [B,S]
    const float* __restrict__ lw,       // [L]
    const float* __restrict__ Wu,       // [N_SEC,K,H]
    const float* __restrict__ bu,       // [N_SEC,H]
    const float* __restrict__ Wreg,     // [H,1]
    const float* __restrict__ Word)     // [H,4]
{
    const int cta = blockIdx.x;
    const int t = threadIdx.x;          // 0..255

    __shared__ int   sm[SROWS];
    __shared__ float W5s[Hc * 5];       // 20 KB, used by precompute branch

    if (cta < POOL_CTAS) {
        // ================= pooling =================
        const int b = cta >> 2;
        const int j = cta & 3;

        float l0 = lw[0], l1 = lw[1], l2 = lw[2], l3 = lw[3];
        float mx = fmaxf(fmaxf(l0, l1), fmaxf(l2, l3));
        float w0 = expf(l0 - mx), w1 = expf(l1 - mx), w2 = expf(l2 - mx), w3 = expf(l3 - mx);
        float winv = 1.0f / (w0 + w1 + w2 + w3);
        w0 *= winv; w1 *= winv; w2 *= winv; w3 *= winv;

        if (t < SROWS) sm[t] = mask[b * Sc + j * SROWS + t];
        __syncthreads();

        const size_t LSTRIDE4 = (size_t)Bc * Sc * (Hc / 4);
        const float4* base = reinterpret_cast<const float4*>(hidden)
                           + ((size_t)b * Sc + (size_t)j * SROWS) * (Hc / 4) + t;

        float4 acc = make_float4(0.f, 0.f, 0.f, 0.f);

        #pragma unroll 4
        for (int s = 0; s < SROWS; s++) {
            if (sm[s]) {
                const float4* p = base + (size_t)s * (Hc / 4);
                float4 x0 = __ldg(p);
                float4 x1 = __ldg(p + LSTRIDE4);
                float4 x2 = __ldg(p + 2 * LSTRIDE4);
                float4 x3 = __ldg(p + 3 * LSTRIDE4);
                acc.x += w0 * x0.x + w1 * x1.x + w2 * x2.x + w3 * x3.x;
                acc.y += w0 * x0.y + w1 * x1.y + w2 * x2.y + w3 * x3.y;
                acc.z += w0 * x0.z + w1 * x1.z + w2 * x2.z + w3 * x3.z;
                acc.w += w0 * x0.w + w1 * x1.w + w2 * x2.w + w3 * x3.w;
            }
        }

        reinterpret_cast<float4*>(g_partial)[((size_t)b * PCHUNKS + j) * (Hc / 4) + t] = acc;
    } else {
        // ================= precompute for one section =================
        const int sec = cta - POOL_CTAS;      // 0..25

        // Load [Wreg | Word] into smem as W5s[h*5 + j]
        for (int h = t; h < Hc; h += 256) {
            W5s[h * 5 + 0] = Wreg[h];
            float4 wo = __ldg(reinterpret_cast<const float4*>(Word) + h);
            W5s[h * 5 + 1] = wo.x;
            W5s[h * 5 + 2] = wo.y;
            W5s[h * 5 + 3] = wo.z;
            W5s[h * 5 + 4] = wo.w;
        }
        __syncthreads();

        const int wid = t >> 5, lid = t & 31;
        const float4* wu4 = reinterpret_cast<const float4*>(Wu)
                          + (size_t)sec * Kc * (Hc / 4);

        // 8 warps x 8 iterations cover k = 0..63
        for (int it = 0; it < 8; it++) {
            int k = wid + 8 * it;
            float p0 = 0.f, p1 = 0.f, p2 = 0.f, p3 = 0.f, p4 = 0.f;
            #pragma unroll
            for (int q = 0; q < 8; q++) {
                int h0 = q * 128 + lid * 4;
                float4 wu = __ldg(wu4 + (size_t)k * (Hc / 4) + (h0 >> 2));
                p0 += wu.x * W5s[h0*5+0] + wu.y * W5s[(h0+1)*5+0]
                    + wu.z * W5s[(h0+2)*5+0] + wu.w * W5s[(h0+3)*5+0];
                p1 += wu.x * W5s[h0*5+1] + wu.y * W5s[(h0+1)*5+1]
                    + wu.z * W5s[(h0+2)*5+1] + wu.w * W5s[(h0+3)*5+1];
                p2 += wu.x * W5s[h0*5+2] + wu.y * W5s[(h0+1)*5+2]
                    + wu.z * W5s[(h0+2)*5+2] + wu.w * W5s[(h0+3)*5+2];
                p3 += wu.x * W5s[h0*5+3] + wu.y * W5s[(h0+1)*5+3]
                    + wu.z * W5s[(h0+2)*5+3] + wu.w * W5s[(h0+3)*5+3];
                p4 += wu.x * W5s[h0*5+4] + wu.y * W5s[(h0+1)*5+4]
                    + wu.z * W5s[(h0+2)*5+4] + wu.w * W5s[(h0+3)*5+4];
            }
            p0 = warp_sum(p0); p1 = warp_sum(p1); p2 = warp_sum(p2);
            p3 = warp_sum(p3); p4 = warp_sum(p4);
            if (lid == 0) {
                float* dst = g_P + ((size_t)sec * Kc + k) * 5;
                dst[0] = p0; dst[1] = p1; dst[2] = p2; dst[3] = p3; dst[4] = p4;
            }
        }

        // buW5: warps 0..4, warp j computes bu[sec] . W5[:,j]
        if (wid < 5) {
            float v = 0.f;
            #pragma unroll 4
            for (int i = 0; i < 32; i++) {
                int h = lid + 32 * i;
                v += bu[(size_t)sec * Hc + h] * W5s[h * 5 + wid];
            }
            v = warp_sum(v);
            if (lid == 0) g_buW5[sec * 5 + wid] = v;
        }
    }
}

// ---------------------------------------------------------------------------
// Kernel 2: per-sample finalize — gather + down-proj + GeLU + linearized heads.
// grid = B, 512 threads.
// ---------------------------------------------------------------------------
__global__ __launch_bounds__(512, 2) void finalize_kernel(
    const int*   __restrict__ mask,        // [B,S]
    const int*   __restrict__ section_id,  // [B]
    const float* __restrict__ Wd,          // [N_SEC,H,K]
    const float* __restrict__ bd,          // [N_SEC,K]
    const float* __restrict__ Wreg,        // [H,1]
    const float* __restrict__ breg,        // [1]
    const float* __restrict__ Word,        // [H,4]
    const float* __restrict__ bord,        // [4]
    float*       __restrict__ out)         // [B] reg ++ [B,4] ord
{
    const int b = blockIdx.x;
    const int t = threadIdx.x;      // 0..511

    __shared__ float4 feats4[Hc / 4];     // 4 KB
    __shared__ float4 red4[512];          // 8 KB (down-proj partials 32hg x 16kq)
    __shared__ float  hk[Kc];
    __shared__ float  Ps[Kc * 5];         // 320 floats
    __shared__ float  buW5s[5];
    __shared__ float  redm[8];
    __shared__ float  wr[5][8];
    __shared__ float  hkP[5];
    __shared__ float  invm_s;

    const float* feats = reinterpret_cast<const float*>(feats4);
    const int sec = section_id[b];

    // ---- mask count (threads 0..255) + P/buW5 load (threads 256..511) ----
    if (t < Sc) {
        float mv = (float)mask[b * Sc + t];
        mv = warp_sum(mv);
        if ((t & 31) == 0) redm[t >> 5] = mv;
    } else {
        // strided load: covers all 320 Ps entries with 256 threads
        for (int i = t - 256; i < Kc * 5; i += 256)
            Ps[i] = g_P[(size_t)sec * Kc * 5 + i];
        if (t - 256 < 5)
            buW5s[t - 256] = g_buW5[sec * 5 + (t - 256)];
    }
    __syncthreads();
    if (t == 0) {
        float s = 0.f;
        #pragma unroll
        for (int i = 0; i < 8; i++) s += redm[i];
        invm_s = 1.0f / fmaxf(s, 1e-6f);
    }
    __syncthreads();
    const float invm = invm_s;

    // ---- gather 4 partials -> feats ----
    if (t < Hc / 4) {
        const float4* pp = reinterpret_cast<const float4*>(g_partial)
                         + (size_t)b * PCHUNKS * (Hc / 4) + t;
        float4 a  = pp[0];
        float4 a1 = pp[1 * (Hc / 4)];
        float4 a2 = pp[2 * (Hc / 4)];
        float4 a3 = pp[3 * (Hc / 4)];
        a.x = (a.x + a1.x + a2.x + a3.x) * invm;
        a.y = (a.y + a1.y + a2.y + a3.y) * invm;
        a.z = (a.z + a1.z + a2.z + a3.z) * invm;
        a.w = (a.w + a1.w + a2.w + a3.w) * invm;
        feats4[t] = a;
    }
    __syncthreads();

    // ---- down-proj: 512 threads = 16 k-quads x 32 h-groups (32 h each) ----
    {
        const int kq = t & 15;
        const int hg = t >> 4;          // 0..31
        const float4* wd4 = reinterpret_cast<const float4*>(Wd + (size_t)sec * Hc * Kc);
        float4 a = make_float4(0.f, 0.f, 0.f, 0.f);
        #pragma unroll 8
        for (int i = 0; i < 32; i++) {
            int h = hg * 32 + i;
            float f = feats[h];
            float4 w = __ldg(wd4 + (size_t)h * 16 + kq);
            a.x += f * w.x; a.y += f * w.y; a.z += f * w.z; a.w += f * w.w;
        }
        red4[hg * 16 + kq] = a;
    }
    __syncthreads();
    if (t < 16) {
        float4 s = make_float4(0.f, 0.f, 0.f, 0.f);
        #pragma unroll
        for (int hg = 0; hg < 32; hg++) {
            float4 x = red4[hg * 16 + t];
            s.x += x.x; s.y += x.y; s.z += x.z; s.w += x.w;
        }
        float4 bdv = __ldg(reinterpret_cast<const float4*>(bd + (size_t)sec * Kc) + t);
        hk[t * 4 + 0] = gelu_exact(s.x + bdv.x);
        hk[t * 4 + 1] = gelu_exact(s.y + bdv.y);
        hk[t * 4 + 2] = gelu_exact(s.z + bdv.z);
        hk[t * 4 + 3] = gelu_exact(s.w + bdv.w);
    }
    __syncthreads();

    // ---- heads: feats part (threads 0..255) + hk.P part (warps 8..12) ----
    if (t < 256) {
        const int c = t;
        float4 fv = feats4[c];
        float4 wrg = __ldg(reinterpret_cast<const float4*>(Wreg) + c);
        float preg = fv.x * wrg.x + fv.y * wrg.y + fv.z * wrg.z + fv.w * wrg.w;

        const float4* word4 = reinterpret_cast<const float4*>(Word);
        float4 o0 = __ldg(word4 + 4 * c + 0);
        float4 o1 = __ldg(word4 + 4 * c + 1);
        float4 o2 = __ldg(word4 + 4 * c + 2);
        float4 o3 = __ldg(word4 + 4 * c + 3);
        float po0 = fv.x * o0.x + fv.y * o1.x + fv.z * o2.x + fv.w * o3.x;
        float po1 = fv.x * o0.y + fv.y * o1.y + fv.z * o2.y + fv.w * o3.y;
        float po2 = fv.x * o0.z + fv.y * o1.z + fv.z * o2.z + fv.w * o3.z;
        float po3 = fv.x * o0.w + fv.y * o1.w + fv.z * o2.w + fv.w * o3.w;

        preg = warp_sum(preg);
        po0  = warp_sum(po0);
        po1  = warp_sum(po1);
        po2  = warp_sum(po2);
        po3  = warp_sum(po3);
        if ((t & 31) == 0) {
            int w = t >> 5;
            wr[0][w] = preg; wr[1][w] = po0; wr[2][w] = po1; wr[3][w] = po2; wr[4][w] = po3;
        }
    } else {
        const int w = (t >> 5) - 8;     // 0..7
        const int l = t & 31;
        if (w < 5) {
            float v = hk[l] * Ps[l * 5 + w] + hk[l + 32] * Ps[(l + 32) * 5 + w];
            v = warp_sum(v);
            if (l == 0) hkP[w] = v;
        }
    }
    __syncthreads();
    if (t == 0) {
        float r = 0.f, o0 = 0.f, o1 = 0.f, o2 = 0.f, o3 = 0.f;
        #pragma unroll
        for (int i = 0; i < 8; i++) {
            r  += wr[0][i]; o0 += wr[1][i]; o1 += wr[2][i]; o2 += wr[3][i]; o3 += wr[4][i];
        }
        out[b] = r + hkP[0] + buW5s[0] + breg[0];
        float* op = out + Bc + (size_t)b * 4;
        op[0] = o0 + hkP[1] + buW5s[1] + bord[0];
        op[1] = o1 + hkP[2] + buW5s[2] + bord[1];
        op[2] = o2 + hkP[3] + buW5s[3] + bord[2];
        op[3] = o3 + hkP[4] + buW5s[4] + bord[3];
    }
}

extern "C" void kernel_launch(void* const* d_in, const int* in_sizes, int n_in,
                              void* d_out, int out_size)
{
    const float* hidden = (const float*)d_in[0];
    const int*   mask   = (const int*)  d_in[1];
    const int*   sec    = (const int*)  d_in[2];
    const float* lw     = (const float*)d_in[3];
    const float* Wd     = (const float*)d_in[4];
    const float* bd     = (const float*)d_in[5];
    const float* Wu     = (const float*)d_in[6];
    const float* bu     = (const float*)d_in[7];
    const float* Wreg   = (const float*)d_in[8];
    const float* breg   = (const float*)d_in[9];
    const float* Word   = (const float*)d_in[10];
    const float* bord   = (const float*)d_in[11];
    float* out = (float*)d_out;

    pool_pre_kernel<<<POOL_CTAS + NSEC, 256>>>(hidden, mask, lw, Wu, bu, Wreg, Word);
    finalize_kernel<<<Bc, 512>>>(mask, sec, Wd, bd, Wreg, breg, Word, bord, out);
}